// round 1
// baseline (speedup 1.0000x reference)
#include <cuda_runtime.h>
#include <math.h>

#define GD 64
#define SD 32
#define NV (GD*GD*GD)      // 262144 child voxels
#define NP (SD*SD*SD)      // 32768 parent voxels

// ---------------- device scratch (no allocations allowed) ----------------
__device__ float g_prob[NV*16];            // prob_f child features
__device__ float g_h[NV*16];               // conv1 output per stage (reused)
__device__ float g_h1[NP*16];
__device__ float g_h2[NP*16];
__device__ unsigned char g_occx[NV];
__device__ unsigned char g_pocc[NP];
__device__ unsigned char g_min[NV];        // bit s = voxel in M_in(s)
__device__ int g_list_in[8][NV];
__device__ int g_list_out[8][NV/4];
__device__ int g_cnt_in[8];
__device__ int g_cnt_out[8];

// ---------------- occupancy ----------------
__global__ void k_occ(const float* __restrict__ x) {
    int v = blockIdx.x*256 + threadIdx.x;
    if (v < 8) { g_cnt_in[v] = 0; g_cnt_out[v] = 0; }
    if (v < NV) g_occx[v] = (x[v] > 0.f) ? 1 : 0;
}

__global__ void k_pocc() {
    int p = blockIdx.x*256 + threadIdx.x;
    if (p >= NP) return;
    int px = p>>10, py = (p>>5)&31, pz = p&31;
    int bx = px<<1, by = py<<1, bz = pz<<1;
    unsigned char o = 0;
    #pragma unroll
    for (int a=0;a<2;a++)
    #pragma unroll
    for (int b=0;b<2;b++)
    #pragma unroll
    for (int c=0;c<2;c++)
        o |= g_occx[((bx+a)<<12)|((by+b)<<6)|(bz+c)];
    g_pocc[p] = o;
}

// ---------------- masks, lists, labels, zero probs ----------------
__global__ void k_mask(float* __restrict__ out) {
    __shared__ int scnt[16];
    __shared__ int sbase[16];
    int tid = threadIdx.x;
    if (tid < 16) scnt[tid] = 0;
    __syncthreads();
    int v = blockIdx.x*256 + tid;
    int x = v>>12, y = (v>>6)&63, z = v&63;
    const int LUT[8] = {0,5,4,3,4,2,1,5};   // parity (ox*4+oy*2+oz) -> group id
    int gid = LUT[((x&1)<<2)|((y&1)<<1)|(z&1)];
    int mid = ((x>>1)+(y>>1)+(z>>1)) % 3;
    bool O = g_pocc[((x>>1)<<10)|((y>>1)<<5)|(z>>1)] != 0;
    bool X = g_occx[v] != 0;
    bool g0 = (gid == 0);

    bool bi[8], bo[8];
    bi[0] = O && g0 && (mid==0);
    bi[1] = (O && g0 && mid==1) || (X && g0 && mid==0);
    bi[2] = (X && g0 && mid<2)  || (O && g0 && mid==2);
    bi[3] = (X && g0)      || (O && gid==1);
    bi[4] = (X && gid<=1)  || (O && gid==2);
    bi[5] = (X && gid<=2)  || (O && gid==3);
    bi[6] = (X && gid<=3)  || (O && gid==4);
    bi[7] = (X && gid<=4)  || (O && gid==5);
    bo[0] = O && g0 && mid==0;
    bo[1] = O && g0 && mid==1;
    bo[2] = O && g0 && mid==2;
    #pragma unroll
    for (int s=3;s<8;s++) bo[s] = O && (gid == s-2);

    unsigned char mb = 0;
    int rin[8], rout[8];
    #pragma unroll
    for (int s=0;s<8;s++) {
        if (bi[s]) { mb |= (1u<<s); rin[s]  = atomicAdd(&scnt[s],   1); }
        if (bo[s]) {               rout[s] = atomicAdd(&scnt[8+s], 1); }
    }
    g_min[v] = mb;
    __syncthreads();
    if (tid < 16) {
        int c = scnt[tid];
        sbase[tid] = c ? atomicAdd(tid<8 ? &g_cnt_in[tid] : &g_cnt_out[tid-8], c) : 0;
    }
    __syncthreads();
    #pragma unroll
    for (int s=0;s<8;s++) {
        if (bi[s]) g_list_in[s][sbase[s]   + rin[s]]  = v;
        if (bo[s]) g_list_out[s][sbase[8+s]+ rout[s]] = v;
    }
    // zero probs half + write labels half
    #pragma unroll
    for (int s=0;s<8;s++) out[(s<<18)+v] = 0.f;
    #pragma unroll
    for (int s=0;s<8;s++) {
        bool lab = (s<3) ? (X && g0 && mid==s) : (X && gid==(s-2));
        out[((8+s)<<18)+v] = lab ? 1.f : 0.f;
    }
}

// ---------------- FEL conv1: 1->16, 3^3, relu, masked ----------------
__global__ void k_fel1(const float* __restrict__ w, const float* __restrict__ b) {
    __shared__ float sw[27*16];
    __shared__ float sb[16];
    int tid = threadIdx.x;
    for (int i=tid;i<432;i+=blockDim.x) sw[i]=w[i];
    if (tid<16) sb[tid]=b[tid];
    __syncthreads();
    int p = blockIdx.x*blockDim.x + tid;
    if (p >= NP) return;
    int px=p>>10, py=(p>>5)&31, pz=p&31;
    float acc[16];
    #pragma unroll
    for (int c=0;c<16;c++) acc[c]=sb[c];
    for (int dx=-1;dx<=1;dx++){ int nx=px+dx; if ((unsigned)nx>=32u) continue;
    for (int dy=-1;dy<=1;dy++){ int ny=py+dy; if ((unsigned)ny>=32u) continue;
    for (int dz=-1;dz<=1;dz++){ int nz=pz+dz; if ((unsigned)nz>=32u) continue;
        if (!g_pocc[(nx<<10)|(ny<<5)|nz]) continue;
        int d = ((dx+1)*3+(dy+1))*3+(dz+1);
        const float* wr = sw + d*16;
        #pragma unroll
        for (int c=0;c<16;c++) acc[c] += wr[c];
    }}}
    bool oc = g_pocc[p] != 0;
    float* o = g_h1 + p*16;
    #pragma unroll
    for (int c=0;c<16;c++) o[c] = oc ? fmaxf(acc[c],0.f) : 0.f;
}

// ---------------- FEL conv2: 16->16, 3^3, masked (no relu) ----------------
__global__ void k_fel2(const float* __restrict__ w, const float* __restrict__ b) {
    __shared__ float sw[27*256];
    int tid = threadIdx.x;
    for (int i=tid;i<6912;i+=blockDim.x) sw[i]=w[i];
    __syncthreads();
    int p = blockIdx.x*blockDim.x + tid;
    if (p >= NP) return;
    float* o = g_h2 + p*16;
    if (!g_pocc[p]) {
        #pragma unroll
        for (int c=0;c<16;c++) o[c]=0.f;
        return;
    }
    float acc[16];
    #pragma unroll
    for (int c=0;c<16;c++) acc[c]=b[c];
    int px=p>>10, py=(p>>5)&31, pz=p&31;
    for (int dx=-1;dx<=1;dx++){ int nx=px+dx; if ((unsigned)nx>=32u) continue;
    for (int dy=-1;dy<=1;dy++){ int ny=py+dy; if ((unsigned)ny>=32u) continue;
    for (int dz=-1;dz<=1;dz++){ int nz=pz+dz; if ((unsigned)nz>=32u) continue;
        int nv = (nx<<10)|(ny<<5)|nz;
        if (!g_pocc[nv]) continue;
        int d = ((dx+1)*3+(dy+1))*3+(dz+1);
        const float* hp = g_h1 + nv*16;
        const float* wr = sw + d*256;
        #pragma unroll
        for (int cin=0;cin<16;cin++){
            float vv = hp[cin];
            #pragma unroll
            for (int c=0;c<16;c++) acc[c] += vv*wr[cin*16+c];
        }
    }}}
    #pragma unroll
    for (int c=0;c<16;c++) o[c]=acc[c];
}

// ---------------- generative upsample k2 s2 ----------------
__global__ void k_up(const float* __restrict__ wup, const float* __restrict__ bup) {
    __shared__ float sw[8*256];
    __shared__ float sb[16];
    int tid = threadIdx.x;
    for (int i=tid;i<2048;i+=blockDim.x) sw[i]=wup[i];
    if (tid<16) sb[tid]=bup[tid];
    __syncthreads();
    int v = blockIdx.x*blockDim.x + tid;
    if (v >= NV) return;
    int x=v>>12, y=(v>>6)&63, z=v&63;
    int p = ((x>>1)<<10)|((y>>1)<<5)|(z>>1);
    float* po = g_prob + v*16;
    if (!g_pocc[p]) {
        #pragma unroll
        for (int c=0;c<16;c++) po[c]=0.f;
        return;
    }
    int o = ((x&1)<<2)|((y&1)<<1)|(z&1);
    float acc[16];
    #pragma unroll
    for (int c=0;c<16;c++) acc[c]=sb[c];
    const float* hp = g_h2 + p*16;
    const float* wo = sw + o*256;
    #pragma unroll
    for (int cin=0;cin<16;cin++){
        float vv = hp[cin];
        #pragma unroll
        for (int c=0;c<16;c++) acc[c] += vv*wo[cin*16+c];
    }
    #pragma unroll
    for (int c=0;c<16;c++) po[c]=acc[c];
}

// ---------------- coder conv1: 16->16, relu, gather over M_in list ----------------
template<int R>
__global__ void k_conv1(const float* __restrict__ w, const float* __restrict__ b, int s) {
    constexpr int K = 2*R+1;
    constexpr int TAPS = K*K*K;
    int cnt = g_cnt_in[s];
    if ((int)(blockIdx.x*blockDim.x) >= cnt) return;
    extern __shared__ float sw[];
    for (int i=threadIdx.x;i<TAPS*256;i+=blockDim.x) sw[i]=w[i];
    __syncthreads();
    int idx = blockIdx.x*blockDim.x + threadIdx.x;
    if (idx >= cnt) return;
    int v = g_list_in[s][idx];
    int x=v>>12, y=(v>>6)&63, z=v&63;
    const float4* b4 = (const float4*)b;
    float4 a0=b4[0], a1=b4[1], a2=b4[2], a3=b4[3];
    for (int dx=-R;dx<=R;dx++){ int nx=x+dx; if ((unsigned)nx>=64u) continue;
    for (int dy=-R;dy<=R;dy++){ int ny=y+dy; if ((unsigned)ny>=64u) continue;
    for (int dz=-R;dz<=R;dz++){ int nz=z+dz; if ((unsigned)nz>=64u) continue;
        int nv = (nx<<12)|(ny<<6)|nz;
        if (!((g_min[nv]>>s)&1)) continue;               // tap not in M_in(s) -> contributes 0
        int d = ((dx+R)*K+(dy+R))*K+(dz+R);
        const float4* pin = (const float4*)(g_prob + nv*16);
        float4 i0=pin[0], i1=pin[1], i2=pin[2], i3=pin[3];
        float in[16] = {i0.x,i0.y,i0.z,i0.w, i1.x,i1.y,i1.z,i1.w,
                        i2.x,i2.y,i2.z,i2.w, i3.x,i3.y,i3.z,i3.w};
        const float4* pw = (const float4*)(sw + d*256);
        #pragma unroll
        for (int c=0;c<16;c++){
            float vv = in[c];
            float4 w0=pw[c*4+0], w1=pw[c*4+1], w2=pw[c*4+2], w3=pw[c*4+3];
            a0.x += vv*w0.x; a0.y += vv*w0.y; a0.z += vv*w0.z; a0.w += vv*w0.w;
            a1.x += vv*w1.x; a1.y += vv*w1.y; a1.z += vv*w1.z; a1.w += vv*w1.w;
            a2.x += vv*w2.x; a2.y += vv*w2.y; a2.z += vv*w2.z; a2.w += vv*w2.w;
            a3.x += vv*w3.x; a3.y += vv*w3.y; a3.z += vv*w3.z; a3.w += vv*w3.w;
        }
    }}}
    a0.x=fmaxf(a0.x,0.f); a0.y=fmaxf(a0.y,0.f); a0.z=fmaxf(a0.z,0.f); a0.w=fmaxf(a0.w,0.f);
    a1.x=fmaxf(a1.x,0.f); a1.y=fmaxf(a1.y,0.f); a1.z=fmaxf(a1.z,0.f); a1.w=fmaxf(a1.w,0.f);
    a2.x=fmaxf(a2.x,0.f); a2.y=fmaxf(a2.y,0.f); a2.z=fmaxf(a2.z,0.f); a2.w=fmaxf(a2.w,0.f);
    a3.x=fmaxf(a3.x,0.f); a3.y=fmaxf(a3.y,0.f); a3.z=fmaxf(a3.z,0.f); a3.w=fmaxf(a3.w,0.f);
    float4* ph = (float4*)(g_h + v*16);
    ph[0]=a0; ph[1]=a1; ph[2]=a2; ph[3]=a3;
}

// ---------------- coder conv2: 16->1, sigmoid, gather over M_out list ----------------
template<int R>
__global__ void k_conv2(const float* __restrict__ w, const float* __restrict__ b2,
                        int s, float* __restrict__ out) {
    constexpr int K = 2*R+1;
    constexpr int TAPS = K*K*K;
    int cnt = g_cnt_out[s];
    if ((int)(blockIdx.x*blockDim.x) >= cnt) return;
    __shared__ float sw[TAPS*16];
    for (int i=threadIdx.x;i<TAPS*16;i+=blockDim.x) sw[i]=w[i];
    __syncthreads();
    int idx = blockIdx.x*blockDim.x + threadIdx.x;
    if (idx >= cnt) return;
    int v = g_list_out[s][idx];
    int x=v>>12, y=(v>>6)&63, z=v&63;
    float acc = b2[0];
    for (int dx=-R;dx<=R;dx++){ int nx=x+dx; if ((unsigned)nx>=64u) continue;
    for (int dy=-R;dy<=R;dy++){ int ny=y+dy; if ((unsigned)ny>=64u) continue;
    for (int dz=-R;dz<=R;dz++){ int nz=z+dz; if ((unsigned)nz>=64u) continue;
        int nv = (nx<<12)|(ny<<6)|nz;
        if (!((g_min[nv]>>s)&1)) continue;               // h is masked by M_in(s)
        int d = ((dx+R)*K+(dy+R))*K+(dz+R);
        const float* hp = g_h + nv*16;
        const float* wr = sw + d*16;
        #pragma unroll
        for (int cin=0;cin<16;cin++) acc += hp[cin]*wr[cin];
    }}}
    out[(s<<18)+v] = 1.f/(1.f + expf(-acc));
}

// ---------------- launch ----------------
extern "C" void kernel_launch(void* const* d_in, const int* in_sizes, int n_in,
                              void* d_out, int out_size) {
    const float* x      = (const float*)d_in[0];
    const float* w_fel1 = (const float*)d_in[3];
    const float* b_fel1 = (const float*)d_in[4];
    const float* w_fel2 = (const float*)d_in[5];
    const float* b_fel2 = (const float*)d_in[6];
    const float* w_up   = (const float*)d_in[7];
    const float* b_up   = (const float*)d_in[8];
    const float* wc1    = (const float*)d_in[9];
    const float* bc1    = (const float*)d_in[10];
    const float* wc2    = (const float*)d_in[11];
    const float* bc2    = (const float*)d_in[12];
    const float* wl1    = (const float*)d_in[13];
    const float* bl1    = (const float*)d_in[14];
    const float* wl2    = (const float*)d_in[15];
    const float* bl2    = (const float*)d_in[16];
    float* out = (float*)d_out;

    cudaFuncSetAttribute((const void*)k_conv1<2>,
                         cudaFuncAttributeMaxDynamicSharedMemorySize, 125*256*4);

    k_occ<<<1024,256>>>(x);
    k_pocc<<<128,256>>>();
    k_mask<<<1024,256>>>(out);
    k_fel1<<<128,256>>>(w_fel1, b_fel1);
    k_fel2<<<128,256>>>(w_fel2, b_fel2);
    k_up<<<1024,256>>>(w_up, b_up);

    // static upper bounds on list lengths (from parity-group structure)
    const int inB[8]  = {32768,32768,32768,65536,98304,131072,196608,262144};
    const int outB[8] = {32768,32768,32768,32768,32768,32768,65536,65536};

    for (int s=0;s<8;s++) {
        if (s==1 || s==2) {
            int j = s-1;
            k_conv1<2><<<(inB[s]+255)/256,256,125*256*4>>>(wl1 + j*125*256, bl1 + j*16, s);
            k_conv2<2><<<(outB[s]+255)/256,256>>>(wl2 + j*125*16, bl2 + j, s, out);
        } else {
            int k = (s==0) ? 0 : (s-2);
            k_conv1<1><<<(inB[s]+255)/256,256,27*256*4>>>(wc1 + k*27*256, bc1 + k*16, s);
            k_conv2<1><<<(outB[s]+255)/256,256>>>(wc2 + k*27*16, bc2 + k, s, out);
        }
    }
}